// round 2
// baseline (speedup 1.0000x reference)
#include <cuda_runtime.h>
#include <math.h>

#define TLEN  64
#define BSZ   32
#define NROWS 2048         // TLEN*BSZ
#define HID   1024
#define SLEN  200
#define VTGT  32000
#define VEXT  2000
#define VOUT  34000        // VTGT + VEXT

// small per-row scratch (allowed: __device__ globals)
__device__ float g_logcopy[NROWS];   // log(clip(sigmoid(z)))
__device__ float g_omc[NROWS];       // 1 - sigmoid(z)

// ---------------------------------------------------------------------------
// 1) copy gate: one warp per row
// ---------------------------------------------------------------------------
__global__ void copy_gate_kernel(const float* __restrict__ h,
                                 const float* __restrict__ w_copy,
                                 const float* __restrict__ b_copy) {
    int warp = (blockIdx.x * blockDim.x + threadIdx.x) >> 5;
    int lane = threadIdx.x & 31;
    if (warp >= NROWS) return;
    const float* hr = h + (size_t)warp * HID;
    float s = 0.f;
#pragma unroll 8
    for (int i = lane; i < HID; i += 32) s += hr[i] * w_copy[i];
#pragma unroll
    for (int off = 16; off; off >>= 1) s += __shfl_xor_sync(0xffffffffu, s, off);
    if (lane == 0) {
        float z = s + b_copy[0];
        float c = 1.f / (1.f + expf(-z));
        g_logcopy[warp] = logf(fminf(fmaxf(c, 0.001f), 0.999f));
        g_omc[warp]     = 1.f - c;
    }
}

// ---------------------------------------------------------------------------
// 2) main GEMM: C[m, n] = sum_k A[m,k] * B[n,k] + bias[n]
//    A = hidden [2048, 1024], B = W_out [32000, 1024] (both K-contiguous / NT)
//    writes into out with row stride VOUT (cols 0..VTGT-1)
//    BM=BN=64, BK=16, 256 threads, 4x4 microtile
// ---------------------------------------------------------------------------
#define BM 64
#define BN 64
#define BK 16
#define SPAD 68   // padded row stride (multiple of 4 keeps float4 alignment)

__global__ __launch_bounds__(256) void gemm_kernel(const float* __restrict__ A,
                                                   const float* __restrict__ B,
                                                   const float* __restrict__ bias,
                                                   float* __restrict__ out) {
    __shared__ float As[BK * SPAD];   // As[k][m]
    __shared__ float Bs[BK * SPAD];   // Bs[k][n]

    const int tid = threadIdx.x;
    const int m0  = blockIdx.y * BM;
    const int n0  = blockIdx.x * BN;

    const int tm = (tid >> 4) << 2;   // 0,4,...,60
    const int tn = (tid & 15) << 2;   // 0,4,...,60

    // global-load mapping: one float4 per thread per tile
    const int lrow = tid >> 2;         // 0..63
    const int lk4  = (tid & 3) << 2;   // 0,4,8,12

    const float* Ap = A + (size_t)(m0 + lrow) * HID + lk4;
    const float* Bp = B + (size_t)(n0 + lrow) * HID + lk4;

    float acc[4][4] = {};

    for (int k0 = 0; k0 < HID; k0 += BK) {
        float4 av = *(const float4*)(Ap + k0);
        float4 bv = *(const float4*)(Bp + k0);

        __syncthreads();   // previous tile's compute done before overwrite
        As[(lk4 + 0) * SPAD + lrow] = av.x;
        As[(lk4 + 1) * SPAD + lrow] = av.y;
        As[(lk4 + 2) * SPAD + lrow] = av.z;
        As[(lk4 + 3) * SPAD + lrow] = av.w;
        Bs[(lk4 + 0) * SPAD + lrow] = bv.x;
        Bs[(lk4 + 1) * SPAD + lrow] = bv.y;
        Bs[(lk4 + 2) * SPAD + lrow] = bv.z;
        Bs[(lk4 + 3) * SPAD + lrow] = bv.w;
        __syncthreads();

#pragma unroll
        for (int k = 0; k < BK; k++) {
            float4 a = *(const float4*)&As[k * SPAD + tm];
            float4 b = *(const float4*)&Bs[k * SPAD + tn];
            float ar[4] = {a.x, a.y, a.z, a.w};
            float br[4] = {b.x, b.y, b.z, b.w};
#pragma unroll
            for (int i = 0; i < 4; i++)
#pragma unroll
                for (int j = 0; j < 4; j++)
                    acc[i][j] += ar[i] * br[j];
        }
    }

    float4 bb = *(const float4*)&bias[n0 + tn];
    float br[4] = {bb.x, bb.y, bb.z, bb.w};
#pragma unroll
    for (int i = 0; i < 4; i++) {
        float4 v;
        v.x = acc[i][0] + br[0];
        v.y = acc[i][1] + br[1];
        v.z = acc[i][2] + br[2];
        v.w = acc[i][3] + br[3];
        *(float4*)&out[(size_t)(m0 + tm + i) * VOUT + (n0 + tn)] = v;
    }
}

// ---------------------------------------------------------------------------
// 3) in-place log-softmax over cols [0, VTGT) of each row, + logcopy
// ---------------------------------------------------------------------------
__global__ __launch_bounds__(256) void softmax_kernel(float* __restrict__ out) {
    const int row = blockIdx.x;
    float* p = out + (size_t)row * VOUT;
    __shared__ float red[256];
    const int tid = threadIdx.x;

    float m = -INFINITY;
    for (int v = tid; v < VTGT; v += 256) m = fmaxf(m, p[v]);
    red[tid] = m;
    __syncthreads();
#pragma unroll
    for (int s = 128; s; s >>= 1) {
        if (tid < s) red[tid] = fmaxf(red[tid], red[tid + s]);
        __syncthreads();
    }
    const float rmax = red[0];
    __syncthreads();

    float sum = 0.f;
    for (int v = tid; v < VTGT; v += 256) sum += expf(p[v] - rmax);
    red[tid] = sum;
    __syncthreads();
#pragma unroll
    for (int s = 128; s; s >>= 1) {
        if (tid < s) red[tid] += red[tid + s];
        __syncthreads();
    }
    const float add = g_logcopy[row] - (rmax + logf(red[0]));

    for (int v = tid; v < VTGT; v += 256) p[v] += add;
}

// ---------------------------------------------------------------------------
// 4) ext-vocab scatter: one block per row, smem accumulation
// ---------------------------------------------------------------------------
__global__ __launch_bounds__(256) void ext_kernel(const float* __restrict__ attn,
                                                  const int* __restrict__ c2e,
                                                  float* __restrict__ out) {
    const int row = blockIdx.x;          // row = t*BSZ + b
    const int b   = row & (BSZ - 1);
    const int tid = threadIdx.x;
    __shared__ float ext[VEXT];

    for (int e = tid; e < VEXT; e += 256) ext[e] = 0.f;
    __syncthreads();

    const float omc = g_omc[row];
    for (int s = tid; s < SLEN; s += 256) {
        int idx = c2e[s * BSZ + b];
        if (idx != 0)  // UNK = 0 ignored
            atomicAdd(&ext[idx], attn[(size_t)row * SLEN + s] * omc);
    }
    __syncthreads();

    float* p = out + (size_t)row * VOUT + VTGT;
    for (int e = tid; e < VEXT; e += 256)
        p[e] = logf(fminf(fmaxf(ext[e], 0.001f), 0.999f));
}

// ---------------------------------------------------------------------------
extern "C" void kernel_launch(void* const* d_in, const int* in_sizes, int n_in,
                              void* d_out, int out_size) {
    const float* hidden  = (const float*)d_in[0];   // [64,32,1024]
    const float* attn    = (const float*)d_in[1];   // [64,32,200]
    const int*   c2e     = (const int*)  d_in[2];   // [200,32]
    const float* W_out   = (const float*)d_in[3];   // [32000,1024]
    const float* b_out   = (const float*)d_in[4];   // [32000]
    const float* w_copy  = (const float*)d_in[5];   // [1,1024]
    const float* b_copy  = (const float*)d_in[6];   // [1]
    float* out = (float*)d_out;                     // [64,32,34000]

    copy_gate_kernel<<<NROWS / 8, 256>>>(hidden, w_copy, b_copy);
    gemm_kernel<<<dim3(VTGT / BN, NROWS / BM), 256>>>(hidden, W_out, b_out, out);
    ext_kernel<<<NROWS, 256>>>(attn, c2e, out);
    softmax_kernel<<<NROWS, 256>>>(out);
}

// round 5
// speedup vs baseline: 2.2342x; 2.2342x over previous
#include <cuda_runtime.h>
#include <cuda_bf16.h>
#include <math.h>
#include <stdint.h>

#define TLEN  64
#define BSZ   32
#define NROWS 2048
#define HID   1024
#define SLEN  200
#define VTGT  32000
#define VEXT  2000
#define VOUT  34000

// ---------------------------------------------------------------------------
// device scratch
// ---------------------------------------------------------------------------
__device__ float g_logcopy[NROWS];
__device__ float g_omc[NROWS];
__device__ __align__(128) __nv_bfloat16 g_Ahi[(size_t)NROWS * HID];
__device__ __align__(128) __nv_bfloat16 g_Alo[(size_t)NROWS * HID];
__device__ __align__(128) __nv_bfloat16 g_Bhi[(size_t)VTGT * HID];
__device__ __align__(128) __nv_bfloat16 g_Blo[(size_t)VTGT * HID];

// ---------------------------------------------------------------------------
// helpers
// ---------------------------------------------------------------------------
__device__ __forceinline__ uint32_t smem_u32(const void* p) {
    uint32_t a;
    asm("{ .reg .u64 t; cvta.to.shared.u64 t, %1; cvt.u32.u64 %0, t; }" : "=r"(a) : "l"(p));
    return a;
}
__device__ __forceinline__ void cp_async16(uint32_t dst, const void* src) {
    asm volatile("cp.async.cg.shared.global [%0], [%1], 16;" :: "r"(dst), "l"(src) : "memory");
}
#define CP_COMMIT() asm volatile("cp.async.commit_group;" ::: "memory")
#define CP_WAIT1()  asm volatile("cp.async.wait_group 1;" ::: "memory")

__device__ __forceinline__ void ldsm_x4(uint32_t* r, uint32_t addr) {
    asm volatile("ldmatrix.sync.aligned.m8n8.x4.shared.b16 {%0,%1,%2,%3}, [%4];"
                 : "=r"(r[0]), "=r"(r[1]), "=r"(r[2]), "=r"(r[3]) : "r"(addr));
}
__device__ __forceinline__ void mma_bf16(float* c, const uint32_t* a, uint32_t b0, uint32_t b1) {
    asm volatile(
        "mma.sync.aligned.m16n8k16.row.col.f32.bf16.bf16.f32 "
        "{%0,%1,%2,%3}, {%4,%5,%6,%7}, {%8,%9}, {%0,%1,%2,%3};"
        : "+f"(c[0]), "+f"(c[1]), "+f"(c[2]), "+f"(c[3])
        : "r"(a[0]), "r"(a[1]), "r"(a[2]), "r"(a[3]), "r"(b0), "r"(b1));
}

// ---------------------------------------------------------------------------
// pack: fp32 -> bf16 hi/lo  (grid-stride, float4 in, ushort4 out)
// ---------------------------------------------------------------------------
__global__ __launch_bounds__(256) void pack_split(const float* __restrict__ src,
                                                  __nv_bfloat16* __restrict__ hi,
                                                  __nv_bfloat16* __restrict__ lo,
                                                  int n4) {
    int stride = gridDim.x * blockDim.x;
    for (int i = blockIdx.x * blockDim.x + threadIdx.x; i < n4; i += stride) {
        float4 v = ((const float4*)src)[i];
        float x[4] = {v.x, v.y, v.z, v.w};
        ushort4 h, l;
        unsigned short* hp = (unsigned short*)&h;
        unsigned short* lp = (unsigned short*)&l;
#pragma unroll
        for (int j = 0; j < 4; j++) {
            __nv_bfloat16 hb = __float2bfloat16(x[j]);
            __nv_bfloat16 lb = __float2bfloat16(x[j] - __bfloat162float(hb));
            hp[j] = *(unsigned short*)&hb;
            lp[j] = *(unsigned short*)&lb;
        }
        ((ushort4*)hi)[i] = h;
        ((ushort4*)lo)[i] = l;
    }
}

// ---------------------------------------------------------------------------
// GEMM: out[m, n0..] = A[m,:] . B[n,:] + bias[n]
// BM=BN=128, BK=32, 3-stage cp.async pipeline, 8 warps (2M x 4N)
// smem per stage: Ah,Al,Bh,Bl each 128 rows x 40 bf16 (80B stride) = 10240B
// ---------------------------------------------------------------------------
#define STAGE_B   40960
#define SMEM_GEMM (3 * STAGE_B)

__device__ __forceinline__ void issue_stage(uint32_t sb, int buf, int k0,
                                            const __nv_bfloat16* baseA_hi,
                                            const __nv_bfloat16* baseA_lo,
                                            const __nv_bfloat16* baseB_hi,
                                            const __nv_bfloat16* baseB_lo,
                                            int tid) {
    const uint32_t dstb = sb + buf * STAGE_B;
    const __nv_bfloat16* bases[4] = {baseA_hi, baseA_lo, baseB_hi, baseB_lo};
#pragma unroll
    for (int i = 0; i < 8; i++) {
        int id  = i * 256 + tid;
        int mat = id >> 9;
        int row = (id >> 2) & 127;
        int c   = id & 3;
        const __nv_bfloat16* src = bases[mat] + (size_t)row * HID + k0 + c * 8;
        cp_async16(dstb + mat * 10240 + row * 80 + c * 16, src);
    }
}

__global__ __launch_bounds__(256, 1) void gemm_mma(const float* __restrict__ bias,
                                                   float* __restrict__ out) {
    extern __shared__ unsigned char smem[];
    const uint32_t sb = smem_u32(smem);
    const int tid = threadIdx.x;
    const int wid = tid >> 5, lid = tid & 31;
    const int wm = wid & 1;          // 0..1  (64-row half)
    const int wn = wid >> 1;         // 0..3  (32-col quarter)
    const int m0 = blockIdx.x * 128;
    const int n0 = blockIdx.y * 128;

    const __nv_bfloat16* bAh = g_Ahi + (size_t)m0 * HID;
    const __nv_bfloat16* bAl = g_Alo + (size_t)m0 * HID;
    const __nv_bfloat16* bBh = g_Bhi + (size_t)n0 * HID;
    const __nv_bfloat16* bBl = g_Blo + (size_t)n0 * HID;

    float acc[4][4][4] = {};

    issue_stage(sb, 0, 0, bAh, bAl, bBh, bBl, tid);  CP_COMMIT();
    issue_stage(sb, 1, 32, bAh, bAl, bBh, bBl, tid); CP_COMMIT();

    // ldmatrix address components (lane-dependent, stage-independent)
    const int lrow = lid & 15;
    const int lcol = (lid >> 4) << 3;     // 0 or 8
    const uint32_t a_row_off = (uint32_t)(wm * 64 + lrow) * 80;
    const uint32_t b_row_off = (uint32_t)(wn * 32 + lrow) * 80;

    int buf = 0;
    for (int kt = 0; kt < 32; kt++) {
        CP_WAIT1();
        __syncthreads();
        int nk = kt + 2;
        if (nk < 32) issue_stage(sb, nk % 3, nk * 32, bAh, bAl, bBh, bBl, tid);
        CP_COMMIT();

        const uint32_t st = sb + buf * STAGE_B;
#pragma unroll
        for (int kk = 0; kk < 32; kk += 16) {
            const uint32_t coff = (uint32_t)(kk + lcol) * 2;
            uint32_t ah[4][4], al[4][4], bh[2][4], bl[2][4];
#pragma unroll
            for (int mi = 0; mi < 4; mi++) {
                uint32_t ao = st + a_row_off + (uint32_t)(mi * 16) * 80 + coff;
                ldsm_x4(ah[mi], ao);
                ldsm_x4(al[mi], ao + 10240);
            }
#pragma unroll
            for (int g = 0; g < 2; g++) {
                uint32_t bo = st + 20480 + b_row_off + (uint32_t)(g * 16) * 80 + coff;
                ldsm_x4(bh[g], bo);
                ldsm_x4(bl[g], bo + 10240);
            }
            // b-frag for tile ni: {r[ni&1], r[2+(ni&1)]} of group ni>>1
#pragma unroll
            for (int mi = 0; mi < 4; mi++)
#pragma unroll
                for (int ni = 0; ni < 4; ni++) {
                    const uint32_t* bg = bh[ni >> 1];
                    mma_bf16(acc[mi][ni], ah[mi], bg[ni & 1], bg[2 + (ni & 1)]);
                }
#pragma unroll
            for (int mi = 0; mi < 4; mi++)
#pragma unroll
                for (int ni = 0; ni < 4; ni++) {
                    const uint32_t* bg = bh[ni >> 1];
                    mma_bf16(acc[mi][ni], al[mi], bg[ni & 1], bg[2 + (ni & 1)]);
                }
#pragma unroll
            for (int mi = 0; mi < 4; mi++)
#pragma unroll
                for (int ni = 0; ni < 4; ni++) {
                    const uint32_t* bg = bl[ni >> 1];
                    mma_bf16(acc[mi][ni], ah[mi], bg[ni & 1], bg[2 + (ni & 1)]);
                }
        }
        buf = (buf + 1) % 3;
    }

    // epilogue: fragment layout -> gmem with bias
    const int qrow = lid >> 2;
    const int qcol = (lid & 3) * 2;
#pragma unroll
    for (int ni = 0; ni < 4; ni++) {
        const int gn = n0 + wn * 32 + ni * 8 + qcol;
        const float b0 = __ldg(&bias[gn]);
        const float b1 = __ldg(&bias[gn + 1]);
#pragma unroll
        for (int mi = 0; mi < 4; mi++) {
            const int gm = m0 + wm * 64 + mi * 16 + qrow;
            float2 v0 = {acc[mi][ni][0] + b0, acc[mi][ni][1] + b1};
            float2 v1 = {acc[mi][ni][2] + b0, acc[mi][ni][3] + b1};
            *(float2*)&out[(size_t)gm * VOUT + gn] = v0;
            *(float2*)&out[(size_t)(gm + 8) * VOUT + gn] = v1;
        }
    }
}

// ---------------------------------------------------------------------------
// copy gate: one warp per row
// ---------------------------------------------------------------------------
__global__ void copy_gate_kernel(const float* __restrict__ h,
                                 const float* __restrict__ w_copy,
                                 const float* __restrict__ b_copy) {
    int warp = (blockIdx.x * blockDim.x + threadIdx.x) >> 5;
    int lane = threadIdx.x & 31;
    if (warp >= NROWS) return;
    const float* hr = h + (size_t)warp * HID;
    float s = 0.f;
#pragma unroll 8
    for (int i = lane; i < HID; i += 32) s += hr[i] * w_copy[i];
#pragma unroll
    for (int off = 16; off; off >>= 1) s += __shfl_xor_sync(0xffffffffu, s, off);
    if (lane == 0) {
        float z = s + b_copy[0];
        float c = 1.f / (1.f + expf(-z));
        g_logcopy[warp] = logf(fminf(fmaxf(c, 0.001f), 0.999f));
        g_omc[warp]     = 1.f - c;
    }
}

// ---------------------------------------------------------------------------
// in-place log-softmax over cols [0, VTGT) + logcopy
// ---------------------------------------------------------------------------
__global__ __launch_bounds__(256) void softmax_kernel(float* __restrict__ out) {
    const int row = blockIdx.x;
    float* p = out + (size_t)row * VOUT;
    __shared__ float red[256];
    const int tid = threadIdx.x;

    float m = -INFINITY;
    for (int v = tid; v < VTGT; v += 256) m = fmaxf(m, p[v]);
    red[tid] = m;
    __syncthreads();
#pragma unroll
    for (int s = 128; s; s >>= 1) {
        if (tid < s) red[tid] = fmaxf(red[tid], red[tid + s]);
        __syncthreads();
    }
    const float rmax = red[0];
    __syncthreads();

    float sum = 0.f;
    for (int v = tid; v < VTGT; v += 256) sum += expf(p[v] - rmax);
    red[tid] = sum;
    __syncthreads();
#pragma unroll
    for (int s = 128; s; s >>= 1) {
        if (tid < s) red[tid] += red[tid + s];
        __syncthreads();
    }
    const float add = g_logcopy[row] - (rmax + logf(red[0]));

    for (int v = tid; v < VTGT; v += 256) p[v] += add;
}

// ---------------------------------------------------------------------------
// ext-vocab scatter
// ---------------------------------------------------------------------------
__global__ __launch_bounds__(256) void ext_kernel(const float* __restrict__ attn,
                                                  const int* __restrict__ c2e,
                                                  float* __restrict__ out) {
    const int row = blockIdx.x;
    const int b   = row & (BSZ - 1);
    const int tid = threadIdx.x;
    __shared__ float ext[VEXT];

    for (int e = tid; e < VEXT; e += 256) ext[e] = 0.f;
    __syncthreads();

    const float omc = g_omc[row];
    for (int s = tid; s < SLEN; s += 256) {
        int idx = c2e[s * BSZ + b];
        if (idx != 0)
            atomicAdd(&ext[idx], attn[(size_t)row * SLEN + s] * omc);
    }
    __syncthreads();

    float* p = out + (size_t)row * VOUT + VTGT;
    for (int e = tid; e < VEXT; e += 256)
        p[e] = logf(fminf(fmaxf(ext[e], 0.001f), 0.999f));
}

// ---------------------------------------------------------------------------
extern "C" void kernel_launch(void* const* d_in, const int* in_sizes, int n_in,
                              void* d_out, int out_size) {
    const float* hidden  = (const float*)d_in[0];
    const float* attn    = (const float*)d_in[1];
    const int*   c2e     = (const int*)  d_in[2];
    const float* W_out   = (const float*)d_in[3];
    const float* b_out   = (const float*)d_in[4];
    const float* w_copy  = (const float*)d_in[5];
    const float* b_copy  = (const float*)d_in[6];
    float* out = (float*)d_out;

    __nv_bfloat16 *Ahi, *Alo, *Bhi, *Blo;
    cudaGetSymbolAddress((void**)&Ahi, g_Ahi);
    cudaGetSymbolAddress((void**)&Alo, g_Alo);
    cudaGetSymbolAddress((void**)&Bhi, g_Bhi);
    cudaGetSymbolAddress((void**)&Blo, g_Blo);

    cudaFuncSetAttribute(gemm_mma, cudaFuncAttributeMaxDynamicSharedMemorySize, SMEM_GEMM);

    copy_gate_kernel<<<NROWS / 8, 256>>>(hidden, w_copy, b_copy);
    pack_split<<<256, 256>>>(hidden, Ahi, Alo, NROWS * HID / 4);
    pack_split<<<2048, 256>>>(W_out, Bhi, Blo, VTGT * HID / 4);
    gemm_mma<<<dim3(NROWS / 128, VTGT / 128), 256, SMEM_GEMM>>>(b_out, out);
    ext_kernel<<<NROWS, 256>>>(attn, c2e, out);
    softmax_kernel<<<NROWS, 256>>>(out);
}

// round 6
// speedup vs baseline: 3.4599x; 1.5486x over previous
#include <cuda_runtime.h>
#include <cuda_bf16.h>
#include <math.h>
#include <stdint.h>

#define TLEN  64
#define BSZ   32
#define NROWS 2048
#define HID   1024
#define SLEN  200
#define VTGT  32000
#define VEXT  2000
#define VOUT  34000

// ---------------------------------------------------------------------------
// device scratch
// ---------------------------------------------------------------------------
__device__ float g_logcopy[NROWS];
__device__ float g_omc[NROWS];
__device__ __align__(128) __nv_bfloat16 g_Ahi[(size_t)NROWS * HID];
__device__ __align__(128) __nv_bfloat16 g_Alo[(size_t)NROWS * HID];
__device__ __align__(128) __nv_bfloat16 g_Bhi[(size_t)VTGT * HID];

// ---------------------------------------------------------------------------
// helpers
// ---------------------------------------------------------------------------
__device__ __forceinline__ uint32_t smem_u32(const void* p) {
    uint32_t a;
    asm("{ .reg .u64 t; cvta.to.shared.u64 t, %1; cvt.u32.u64 %0, t; }" : "=r"(a) : "l"(p));
    return a;
}
__device__ __forceinline__ void cp_async16(uint32_t dst, const void* src) {
    asm volatile("cp.async.cg.shared.global [%0], [%1], 16;" :: "r"(dst), "l"(src) : "memory");
}
#define CP_COMMIT() asm volatile("cp.async.commit_group;" ::: "memory")
#define CP_WAIT1()  asm volatile("cp.async.wait_group 1;" ::: "memory")

__device__ __forceinline__ void ldsm_x4(uint32_t* r, uint32_t addr) {
    asm volatile("ldmatrix.sync.aligned.m8n8.x4.shared.b16 {%0,%1,%2,%3}, [%4];"
                 : "=r"(r[0]), "=r"(r[1]), "=r"(r[2]), "=r"(r[3]) : "r"(addr));
}
__device__ __forceinline__ void mma_bf16(float* c, const uint32_t* a, uint32_t b0, uint32_t b1) {
    asm volatile(
        "mma.sync.aligned.m16n8k16.row.col.f32.bf16.bf16.f32 "
        "{%0,%1,%2,%3}, {%4,%5,%6,%7}, {%8,%9}, {%0,%1,%2,%3};"
        : "+f"(c[0]), "+f"(c[1]), "+f"(c[2]), "+f"(c[3])
        : "r"(a[0]), "r"(a[1]), "r"(a[2]), "r"(a[3]), "r"(b0), "r"(b1));
}

// ---------------------------------------------------------------------------
// pack A: fp32 -> bf16 hi + lo
// ---------------------------------------------------------------------------
__global__ __launch_bounds__(256) void pack_split(const float* __restrict__ src,
                                                  __nv_bfloat16* __restrict__ hi,
                                                  __nv_bfloat16* __restrict__ lo,
                                                  int n4) {
    int stride = gridDim.x * blockDim.x;
    for (int i = blockIdx.x * blockDim.x + threadIdx.x; i < n4; i += stride) {
        float4 v = ((const float4*)src)[i];
        float x[4] = {v.x, v.y, v.z, v.w};
        ushort4 h, l;
        unsigned short* hp = (unsigned short*)&h;
        unsigned short* lp = (unsigned short*)&l;
#pragma unroll
        for (int j = 0; j < 4; j++) {
            __nv_bfloat16 hb = __float2bfloat16(x[j]);
            __nv_bfloat16 lb = __float2bfloat16(x[j] - __bfloat162float(hb));
            hp[j] = *(unsigned short*)&hb;
            lp[j] = *(unsigned short*)&lb;
        }
        ((ushort4*)hi)[i] = h;
        ((ushort4*)lo)[i] = l;
    }
}

// pack B: fp32 -> bf16 hi only
__global__ __launch_bounds__(256) void pack_hi(const float* __restrict__ src,
                                               __nv_bfloat16* __restrict__ hi,
                                               int n4) {
    int stride = gridDim.x * blockDim.x;
    for (int i = blockIdx.x * blockDim.x + threadIdx.x; i < n4; i += stride) {
        float4 v = ((const float4*)src)[i];
        ushort4 h;
        unsigned short* hp = (unsigned short*)&h;
        hp[0] = __bfloat16_as_ushort(__float2bfloat16(v.x));
        hp[1] = __bfloat16_as_ushort(__float2bfloat16(v.y));
        hp[2] = __bfloat16_as_ushort(__float2bfloat16(v.z));
        hp[3] = __bfloat16_as_ushort(__float2bfloat16(v.w));
        ((ushort4*)hi)[i] = h;
    }
}

// ---------------------------------------------------------------------------
// GEMM: out[m, n] = A[m,:] . B[n,:] + bias[n]
// BM=128, BN=256, BK=32, 512 threads (16 warps: 2M x 8N, warp tile 64x32)
// 2-term split: Ah.Bh + Al.Bh   (B rounded to bf16)
// stage smem: Ah(10240) | Al(10240) | Bh(20480) = 40960B; 3 stages
// ---------------------------------------------------------------------------
#define STAGE_B   40960
#define SMEM_GEMM (3 * STAGE_B)

__device__ __forceinline__ void issue_stage(uint32_t sb, int buf, int k0,
                                            const __nv_bfloat16* bAh,
                                            const __nv_bfloat16* bAl,
                                            const __nv_bfloat16* bBh,
                                            int tid) {
    const uint32_t dstb = sb + buf * STAGE_B;
    {   // Ah: 512 loads (128 rows x 4 chunks), one per thread
        int row = tid >> 2, c = tid & 3;
        cp_async16(dstb + row * 80 + c * 16, bAh + (size_t)row * HID + k0 + c * 8);
        cp_async16(dstb + 10240 + row * 80 + c * 16, bAl + (size_t)row * HID + k0 + c * 8);
    }
#pragma unroll
    for (int j = 0; j < 2; j++) {   // Bh: 1024 loads (256 rows x 4 chunks)
        int id = j * 512 + tid;
        int row = id >> 2, c = id & 3;
        cp_async16(dstb + 20480 + row * 80 + c * 16, bBh + (size_t)row * HID + k0 + c * 8);
    }
}

__global__ __launch_bounds__(512, 1) void gemm_mma(const float* __restrict__ bias,
                                                   float* __restrict__ out) {
    extern __shared__ unsigned char smem[];
    const uint32_t sb = smem_u32(smem);
    const int tid = threadIdx.x;
    const int wid = tid >> 5, lid = tid & 31;
    const int wm = wid & 1;          // 0..1  (64-row half)
    const int wn = wid >> 1;         // 0..7  (32-col slice)
    const int m0 = blockIdx.x * 128;
    const int n0 = blockIdx.y * 256;

    const __nv_bfloat16* bAh = g_Ahi + (size_t)m0 * HID;
    const __nv_bfloat16* bAl = g_Alo + (size_t)m0 * HID;
    const __nv_bfloat16* bBh = g_Bhi + (size_t)n0 * HID;

    float acc[4][4][4] = {};

    issue_stage(sb, 0, 0, bAh, bAl, bBh, tid);  CP_COMMIT();
    issue_stage(sb, 1, 32, bAh, bAl, bBh, tid); CP_COMMIT();

    const int lrow = lid & 15;
    const int lcol = (lid >> 4) << 3;     // 0 or 8
    const uint32_t a_row_off = (uint32_t)(wm * 64 + lrow) * 80;
    const uint32_t b_row_off = 20480u + (uint32_t)(wn * 32 + lrow) * 80;

    int buf = 0;
    for (int kt = 0; kt < 32; kt++) {
        CP_WAIT1();
        __syncthreads();
        int nk = kt + 2;
        if (nk < 32) issue_stage(sb, nk % 3, nk * 32, bAh, bAl, bBh, tid);
        CP_COMMIT();

        const uint32_t st = sb + buf * STAGE_B;
#pragma unroll
        for (int kk = 0; kk < 32; kk += 16) {
            const uint32_t coff = (uint32_t)(kk + lcol) * 2;
            uint32_t ah[4][4], al[4][4], bh[2][4];
#pragma unroll
            for (int mi = 0; mi < 4; mi++) {
                uint32_t ao = st + a_row_off + (uint32_t)(mi * 16) * 80 + coff;
                ldsm_x4(ah[mi], ao);
                ldsm_x4(al[mi], ao + 10240);
            }
#pragma unroll
            for (int g = 0; g < 2; g++)
                ldsm_x4(bh[g], st + b_row_off + (uint32_t)(g * 16) * 80 + coff);
#pragma unroll
            for (int mi = 0; mi < 4; mi++)
#pragma unroll
                for (int ni = 0; ni < 4; ni++) {
                    const uint32_t* bg = bh[ni >> 1];
                    mma_bf16(acc[mi][ni], ah[mi], bg[ni & 1], bg[2 + (ni & 1)]);
                }
#pragma unroll
            for (int mi = 0; mi < 4; mi++)
#pragma unroll
                for (int ni = 0; ni < 4; ni++) {
                    const uint32_t* bg = bh[ni >> 1];
                    mma_bf16(acc[mi][ni], al[mi], bg[ni & 1], bg[2 + (ni & 1)]);
                }
        }
        buf = (buf + 1) % 3;
    }

    // epilogue
    const int qrow = lid >> 2;
    const int qcol = (lid & 3) * 2;
#pragma unroll
    for (int ni = 0; ni < 4; ni++) {
        const int gn = n0 + wn * 32 + ni * 8 + qcol;
        const float b0 = __ldg(&bias[gn]);
        const float b1 = __ldg(&bias[gn + 1]);
#pragma unroll
        for (int mi = 0; mi < 4; mi++) {
            const int gm = m0 + wm * 64 + mi * 16 + qrow;
            float2 v0 = {acc[mi][ni][0] + b0, acc[mi][ni][1] + b1};
            float2 v1 = {acc[mi][ni][2] + b0, acc[mi][ni][3] + b1};
            *(float2*)&out[(size_t)gm * VOUT + gn] = v0;
            *(float2*)&out[(size_t)(gm + 8) * VOUT + gn] = v1;
        }
    }
}

// ---------------------------------------------------------------------------
// copy gate: one warp per row
// ---------------------------------------------------------------------------
__global__ void copy_gate_kernel(const float* __restrict__ h,
                                 const float* __restrict__ w_copy,
                                 const float* __restrict__ b_copy) {
    int warp = (blockIdx.x * blockDim.x + threadIdx.x) >> 5;
    int lane = threadIdx.x & 31;
    if (warp >= NROWS) return;
    const float* hr = h + (size_t)warp * HID;
    float s = 0.f;
#pragma unroll 8
    for (int i = lane; i < HID; i += 32) s += hr[i] * w_copy[i];
#pragma unroll
    for (int off = 16; off; off >>= 1) s += __shfl_xor_sync(0xffffffffu, s, off);
    if (lane == 0) {
        float z = s + b_copy[0];
        float c = 1.f / (1.f + expf(-z));
        g_logcopy[warp] = logf(fminf(fmaxf(c, 0.001f), 0.999f));
        g_omc[warp]     = 1.f - c;
    }
}

// ---------------------------------------------------------------------------
// log-softmax (online stats pass + write pass) over cols [0, VTGT) + logcopy
// ---------------------------------------------------------------------------
__global__ __launch_bounds__(256) void softmax_kernel(float* __restrict__ out) {
    const int row = blockIdx.x;
    float* p = out + (size_t)row * VOUT;
    __shared__ float redm[256];
    __shared__ float reds[256];
    const int tid = threadIdx.x;

    // pass 1: per-thread online max + scaled sum (float4 reads)
    float ml = -INFINITY, sl = 0.f;
    const float4* p4 = (const float4*)p;
    for (int v = tid; v < VTGT / 4; v += 256) {
        float4 x = p4[v];
        float xm = fmaxf(fmaxf(x.x, x.y), fmaxf(x.z, x.w));
        float nm = fmaxf(ml, xm);
        sl = sl * __expf(ml - nm)
           + __expf(x.x - nm) + __expf(x.y - nm)
           + __expf(x.z - nm) + __expf(x.w - nm);
        ml = nm;
    }
    redm[tid] = ml;
    __syncthreads();
#pragma unroll
    for (int s = 128; s; s >>= 1) {
        if (tid < s) redm[tid] = fmaxf(redm[tid], redm[tid + s]);
        __syncthreads();
    }
    const float M = redm[0];
    reds[tid] = sl * __expf(ml - M);
    __syncthreads();
#pragma unroll
    for (int s = 128; s; s >>= 1) {
        if (tid < s) reds[tid] += reds[tid + s];
        __syncthreads();
    }
    const float add = g_logcopy[row] - (M + logf(reds[0]));

    // pass 2: add
    float4* q4 = (float4*)p;
    for (int v = tid; v < VTGT / 4; v += 256) {
        float4 x = q4[v];
        x.x += add; x.y += add; x.z += add; x.w += add;
        q4[v] = x;
    }
}

// ---------------------------------------------------------------------------
// ext-vocab scatter
// ---------------------------------------------------------------------------
__global__ __launch_bounds__(256) void ext_kernel(const float* __restrict__ attn,
                                                  const int* __restrict__ c2e,
                                                  float* __restrict__ out) {
    const int row = blockIdx.x;
    const int b   = row & (BSZ - 1);
    const int tid = threadIdx.x;
    __shared__ float ext[VEXT];

    for (int e = tid; e < VEXT; e += 256) ext[e] = 0.f;
    __syncthreads();

    const float omc = g_omc[row];
    for (int s = tid; s < SLEN; s += 256) {
        int idx = c2e[s * BSZ + b];
        if (idx != 0)
            atomicAdd(&ext[idx], attn[(size_t)row * SLEN + s] * omc);
    }
    __syncthreads();

    float* p = out + (size_t)row * VOUT + VTGT;
    for (int e = tid; e < VEXT; e += 256)
        p[e] = logf(fminf(fmaxf(ext[e], 0.001f), 0.999f));
}

// ---------------------------------------------------------------------------
extern "C" void kernel_launch(void* const* d_in, const int* in_sizes, int n_in,
                              void* d_out, int out_size) {
    const float* hidden  = (const float*)d_in[0];
    const float* attn    = (const float*)d_in[1];
    const int*   c2e     = (const int*)  d_in[2];
    const float* W_out   = (const float*)d_in[3];
    const float* b_out   = (const float*)d_in[4];
    const float* w_copy  = (const float*)d_in[5];
    const float* b_copy  = (const float*)d_in[6];
    float* out = (float*)d_out;

    __nv_bfloat16 *Ahi, *Alo, *Bhi;
    cudaGetSymbolAddress((void**)&Ahi, g_Ahi);
    cudaGetSymbolAddress((void**)&Alo, g_Alo);
    cudaGetSymbolAddress((void**)&Bhi, g_Bhi);

    cudaFuncSetAttribute(gemm_mma, cudaFuncAttributeMaxDynamicSharedMemorySize, SMEM_GEMM);

    copy_gate_kernel<<<NROWS / 8, 256>>>(hidden, w_copy, b_copy);
    pack_split<<<256, 256>>>(hidden, Ahi, Alo, NROWS * HID / 4);
    pack_hi<<<2048, 256>>>(W_out, Bhi, VTGT * HID / 4);
    gemm_mma<<<dim3(NROWS / 128, VTGT / 256), 512, SMEM_GEMM>>>(b_out, out);
    ext_kernel<<<NROWS, 256>>>(attn, c2e, out);
    softmax_kernel<<<NROWS, 256>>>(out);
}

// round 7
// speedup vs baseline: 3.8421x; 1.1105x over previous
#include <cuda_runtime.h>
#include <cuda_bf16.h>
#include <math.h>
#include <stdint.h>

#define TLEN  64
#define BSZ   32
#define NROWS 2048
#define HID   1024
#define SLEN  200
#define VTGT  32000
#define VEXT  2000
#define VOUT  34000
#define NT_N  125          // N tiles of 256

// ---------------------------------------------------------------------------
// device scratch
// ---------------------------------------------------------------------------
__device__ float g_logcopy[NROWS];
__device__ float g_omc[NROWS];
__device__ float2 g_part[(size_t)NROWS * NT_N];     // per-(row, ntile) softmax partials
__device__ __align__(128) __nv_bfloat16 g_Ahi[(size_t)NROWS * HID];
__device__ __align__(128) __nv_bfloat16 g_Alo[(size_t)NROWS * HID];
__device__ __align__(128) __nv_bfloat16 g_Bhi[(size_t)VTGT * HID];

// ---------------------------------------------------------------------------
// helpers
// ---------------------------------------------------------------------------
__device__ __forceinline__ uint32_t smem_u32(const void* p) {
    uint32_t a;
    asm("{ .reg .u64 t; cvta.to.shared.u64 t, %1; cvt.u32.u64 %0, t; }" : "=r"(a) : "l"(p));
    return a;
}
__device__ __forceinline__ void cp_async16(uint32_t dst, const void* src) {
    asm volatile("cp.async.cg.shared.global [%0], [%1], 16;" :: "r"(dst), "l"(src) : "memory");
}
#define CP_COMMIT() asm volatile("cp.async.commit_group;" ::: "memory")
#define CP_WAIT1()  asm volatile("cp.async.wait_group 1;" ::: "memory")

__device__ __forceinline__ void ldsm_x4(uint32_t* r, uint32_t addr) {
    asm volatile("ldmatrix.sync.aligned.m8n8.x4.shared.b16 {%0,%1,%2,%3}, [%4];"
                 : "=r"(r[0]), "=r"(r[1]), "=r"(r[2]), "=r"(r[3]) : "r"(addr));
}
__device__ __forceinline__ void mma_bf16(float* c, const uint32_t* a, uint32_t b0, uint32_t b1) {
    asm volatile(
        "mma.sync.aligned.m16n8k16.row.col.f32.bf16.bf16.f32 "
        "{%0,%1,%2,%3}, {%4,%5,%6,%7}, {%8,%9}, {%0,%1,%2,%3};"
        : "+f"(c[0]), "+f"(c[1]), "+f"(c[2]), "+f"(c[3])
        : "r"(a[0]), "r"(a[1]), "r"(a[2]), "r"(a[3]), "r"(b0), "r"(b1));
}

// ---------------------------------------------------------------------------
// pack A: fp32 -> bf16 hi + lo
// ---------------------------------------------------------------------------
__global__ __launch_bounds__(256) void pack_split(const float* __restrict__ src,
                                                  __nv_bfloat16* __restrict__ hi,
                                                  __nv_bfloat16* __restrict__ lo,
                                                  int n4) {
    int stride = gridDim.x * blockDim.x;
    for (int i = blockIdx.x * blockDim.x + threadIdx.x; i < n4; i += stride) {
        float4 v = ((const float4*)src)[i];
        float x[4] = {v.x, v.y, v.z, v.w};
        ushort4 h, l;
        unsigned short* hp = (unsigned short*)&h;
        unsigned short* lp = (unsigned short*)&l;
#pragma unroll
        for (int j = 0; j < 4; j++) {
            __nv_bfloat16 hb = __float2bfloat16(x[j]);
            __nv_bfloat16 lb = __float2bfloat16(x[j] - __bfloat162float(hb));
            hp[j] = *(unsigned short*)&hb;
            lp[j] = *(unsigned short*)&lb;
        }
        ((ushort4*)hi)[i] = h;
        ((ushort4*)lo)[i] = l;
    }
}

// pack B: fp32 -> bf16 hi only
__global__ __launch_bounds__(256) void pack_hi(const float* __restrict__ src,
                                               __nv_bfloat16* __restrict__ hi,
                                               int n4) {
    int stride = gridDim.x * blockDim.x;
    for (int i = blockIdx.x * blockDim.x + threadIdx.x; i < n4; i += stride) {
        float4 v = ((const float4*)src)[i];
        ushort4 h;
        unsigned short* hp = (unsigned short*)&h;
        hp[0] = __bfloat16_as_ushort(__float2bfloat16(v.x));
        hp[1] = __bfloat16_as_ushort(__float2bfloat16(v.y));
        hp[2] = __bfloat16_as_ushort(__float2bfloat16(v.z));
        hp[3] = __bfloat16_as_ushort(__float2bfloat16(v.w));
        ((ushort4*)hi)[i] = h;
    }
}

// ---------------------------------------------------------------------------
// GEMM: out[m, n] = A[m,:] . B[n,:] + bias[n]   (+ per-(row,ntile) softmax partials)
// BM=128, BN=256, BK=32, 512 threads (16 warps: 4M x 4N, warp tile 32x64)
// 2-term split: Ah.Bh + Al.Bh
// stage smem: Ah(10240) | Al(10240) | Bh(20480) = 40960B; 3 stages
// ---------------------------------------------------------------------------
#define STAGE_B   40960
#define SMEM_GEMM (3 * STAGE_B)

__device__ __forceinline__ void issue_stage(uint32_t sb, int buf, int k0,
                                            const __nv_bfloat16* bAh,
                                            const __nv_bfloat16* bAl,
                                            const __nv_bfloat16* bBh,
                                            int tid) {
    const uint32_t dstb = sb + buf * STAGE_B;
    {
        int row = tid >> 2, c = tid & 3;
        cp_async16(dstb + row * 80 + c * 16, bAh + (size_t)row * HID + k0 + c * 8);
        cp_async16(dstb + 10240 + row * 80 + c * 16, bAl + (size_t)row * HID + k0 + c * 8);
    }
#pragma unroll
    for (int j = 0; j < 2; j++) {
        int id = j * 512 + tid;
        int row = id >> 2, c = id & 3;
        cp_async16(dstb + 20480 + row * 80 + c * 16, bBh + (size_t)row * HID + k0 + c * 8);
    }
}

__global__ __launch_bounds__(512, 1) void gemm_mma(const float* __restrict__ bias,
                                                   float* __restrict__ out) {
    extern __shared__ unsigned char smem[];
    const uint32_t sb = smem_u32(smem);
    const int tid = threadIdx.x;
    const int wid = tid >> 5, lid = tid & 31;
    const int wm = wid & 3;          // 0..3  (32-row slice)
    const int wn = wid >> 2;         // 0..3  (64-col slice)
    const int m0 = blockIdx.x * 128;
    const int n0 = blockIdx.y * 256;

    const __nv_bfloat16* bAh = g_Ahi + (size_t)m0 * HID;
    const __nv_bfloat16* bAl = g_Alo + (size_t)m0 * HID;
    const __nv_bfloat16* bBh = g_Bhi + (size_t)n0 * HID;

    float acc[2][8][4] = {};

    issue_stage(sb, 0, 0, bAh, bAl, bBh, tid);  CP_COMMIT();
    issue_stage(sb, 1, 32, bAh, bAl, bBh, tid); CP_COMMIT();

    const int lrow = lid & 15;
    const int lcol = (lid >> 4) << 3;     // 0 or 8
    const uint32_t a_row_off = (uint32_t)(wm * 32 + lrow) * 80;
    const uint32_t b_row_off = 20480u + (uint32_t)(wn * 64 + lrow) * 80;

    int buf = 0;
    for (int kt = 0; kt < 32; kt++) {
        CP_WAIT1();
        __syncthreads();
        int nk = kt + 2;
        if (nk < 32) issue_stage(sb, nk % 3, nk * 32, bAh, bAl, bBh, tid);
        CP_COMMIT();

        const uint32_t st = sb + buf * STAGE_B;
#pragma unroll
        for (int kk = 0; kk < 32; kk += 16) {
            const uint32_t coff = (uint32_t)(kk + lcol) * 2;
            uint32_t ah[2][4], al[2][4], bh[4][4];
#pragma unroll
            for (int mi = 0; mi < 2; mi++) {
                uint32_t ao = st + a_row_off + (uint32_t)(mi * 16) * 80 + coff;
                ldsm_x4(ah[mi], ao);
                ldsm_x4(al[mi], ao + 10240);
            }
#pragma unroll
            for (int g = 0; g < 4; g++)
                ldsm_x4(bh[g], st + b_row_off + (uint32_t)(g * 16) * 80 + coff);
#pragma unroll
            for (int mi = 0; mi < 2; mi++)
#pragma unroll
                for (int g = 0; g < 4; g++)
#pragma unroll
                    for (int j = 0; j < 2; j++)
                        mma_bf16(acc[mi][2 * g + j], ah[mi], bh[g][j], bh[g][2 + j]);
#pragma unroll
            for (int mi = 0; mi < 2; mi++)
#pragma unroll
                for (int g = 0; g < 4; g++)
#pragma unroll
                    for (int j = 0; j < 2; j++)
                        mma_bf16(acc[mi][2 * g + j], al[mi], bh[g][j], bh[g][2 + j]);
        }
        buf = (buf + 1) % 3;
    }

    // ---- epilogue: bias add + store + per-row softmax partials ----
    const int qrow = lid >> 2;
    const int qcol = (lid & 3) * 2;
#pragma unroll
    for (int ni = 0; ni < 8; ni++) {
        const int gn = n0 + wn * 64 + ni * 8 + qcol;
        const float b0 = __ldg(&bias[gn]);
        const float b1 = __ldg(&bias[gn + 1]);
#pragma unroll
        for (int mi = 0; mi < 2; mi++) {
            const int gm = m0 + wm * 32 + mi * 16 + qrow;
            acc[mi][ni][0] += b0; acc[mi][ni][1] += b1;
            acc[mi][ni][2] += b0; acc[mi][ni][3] += b1;
            *(float2*)&out[(size_t)gm * VOUT + gn] = make_float2(acc[mi][ni][0], acc[mi][ni][1]);
            *(float2*)&out[(size_t)(gm + 8) * VOUT + gn] = make_float2(acc[mi][ni][2], acc[mi][ni][3]);
        }
    }

    // per-row (max, sum exp) over this CTA's 256-col slice
    __syncthreads();                       // stage buf 0 no longer read; reuse as [128][4] float2
    float2* sm2 = (float2*)smem;
#pragma unroll
    for (int mi = 0; mi < 2; mi++)
#pragma unroll
        for (int h = 0; h < 2; h++) {
            float m = -1e30f;
#pragma unroll
            for (int ni = 0; ni < 8; ni++)
                m = fmaxf(m, fmaxf(acc[mi][ni][2 * h], acc[mi][ni][2 * h + 1]));
            float s = 0.f;
#pragma unroll
            for (int ni = 0; ni < 8; ni++)
                s += __expf(acc[mi][ni][2 * h] - m) + __expf(acc[mi][ni][2 * h + 1] - m);
#pragma unroll
            for (int o = 1; o <= 2; o <<= 1) {
                float om = __shfl_xor_sync(0xffffffffu, m, o);
                float os = __shfl_xor_sync(0xffffffffu, s, o);
                float nm = fmaxf(m, om);
                s = s * __expf(m - nm) + os * __expf(om - nm);
                m = nm;
            }
            if ((lid & 3) == 0)
                sm2[(wm * 32 + mi * 16 + h * 8 + qrow) * 4 + wn] = make_float2(m, s);
        }
    __syncthreads();
    if (tid < 128) {
        float m = -1e30f, s = 0.f;
#pragma unroll
        for (int w = 0; w < 4; w++) {
            float2 p = sm2[tid * 4 + w];
            float nm = fmaxf(m, p.x);
            s = s * __expf(m - nm) + p.y * __expf(p.x - nm);
            m = nm;
        }
        g_part[(size_t)(m0 + tid) * NT_N + blockIdx.y] = make_float2(m, s);
    }
}

// ---------------------------------------------------------------------------
// copy gate: one warp per row
// ---------------------------------------------------------------------------
__global__ void copy_gate_kernel(const float* __restrict__ h,
                                 const float* __restrict__ w_copy,
                                 const float* __restrict__ b_copy) {
    int warp = (blockIdx.x * blockDim.x + threadIdx.x) >> 5;
    int lane = threadIdx.x & 31;
    if (warp >= NROWS) return;
    const float* hr = h + (size_t)warp * HID;
    float s = 0.f;
#pragma unroll 8
    for (int i = lane; i < HID; i += 32) s += hr[i] * w_copy[i];
#pragma unroll
    for (int off = 16; off; off >>= 1) s += __shfl_xor_sync(0xffffffffu, s, off);
    if (lane == 0) {
        float z = s + b_copy[0];
        float c = 1.f / (1.f + expf(-z));
        g_logcopy[warp] = logf(fminf(fmaxf(c, 0.001f), 0.999f));
        g_omc[warp]     = 1.f - c;
    }
}

// ---------------------------------------------------------------------------
// softmax finalize: reduce 125 partials per row, then add-sweep
// ---------------------------------------------------------------------------
__global__ __launch_bounds__(256) void softmax_fin(float* __restrict__ out) {
    const int row = blockIdx.x;
    const int tid = threadIdx.x;
    __shared__ float rm[256], rs[256];

    float m = -1e30f, s = 0.f;
    if (tid < NT_N) {
        float2 p = g_part[(size_t)row * NT_N + tid];
        m = p.x; s = p.y;
    }
    rm[tid] = m; rs[tid] = s;
    __syncthreads();
#pragma unroll
    for (int st = 128; st; st >>= 1) {
        if (tid < st) {
            float m2 = rm[tid + st], s2 = rs[tid + st];
            float nm = fmaxf(rm[tid], m2);
            rs[tid] = rs[tid] * __expf(rm[tid] - nm) + s2 * __expf(m2 - nm);
            rm[tid] = nm;
        }
        __syncthreads();
    }
    const float add = g_logcopy[row] - (rm[0] + logf(rs[0]));

    float4* q4 = (float4*)(out + (size_t)row * VOUT);
    for (int v = tid; v < VTGT / 4; v += 256) {
        float4 x = q4[v];
        x.x += add; x.y += add; x.z += add; x.w += add;
        q4[v] = x;
    }
}

// ---------------------------------------------------------------------------
// ext-vocab scatter
// ---------------------------------------------------------------------------
__global__ __launch_bounds__(256) void ext_kernel(const float* __restrict__ attn,
                                                  const int* __restrict__ c2e,
                                                  float* __restrict__ out) {
    const int row = blockIdx.x;
    const int b   = row & (BSZ - 1);
    const int tid = threadIdx.x;
    __shared__ float ext[VEXT];

    for (int e = tid; e < VEXT; e += 256) ext[e] = 0.f;
    __syncthreads();

    const float omc = g_omc[row];
    for (int s = tid; s < SLEN; s += 256) {
        int idx = c2e[s * BSZ + b];
        if (idx != 0)
            atomicAdd(&ext[idx], attn[(size_t)row * SLEN + s] * omc);
    }
    __syncthreads();

    float* p = out + (size_t)row * VOUT + VTGT;
    for (int e = tid; e < VEXT; e += 256)
        p[e] = logf(fminf(fmaxf(ext[e], 0.001f), 0.999f));
}

// ---------------------------------------------------------------------------
extern "C" void kernel_launch(void* const* d_in, const int* in_sizes, int n_in,
                              void* d_out, int out_size) {
    const float* hidden  = (const float*)d_in[0];
    const float* attn    = (const float*)d_in[1];
    const int*   c2e     = (const int*)  d_in[2];
    const float* W_out   = (const float*)d_in[3];
    const float* b_out   = (const float*)d_in[4];
    const float* w_copy  = (const float*)d_in[5];
    const float* b_copy  = (const float*)d_in[6];
    float* out = (float*)d_out;

    __nv_bfloat16 *Ahi, *Alo, *Bhi;
    cudaGetSymbolAddress((void**)&Ahi, g_Ahi);
    cudaGetSymbolAddress((void**)&Alo, g_Alo);
    cudaGetSymbolAddress((void**)&Bhi, g_Bhi);

    cudaFuncSetAttribute(gemm_mma, cudaFuncAttributeMaxDynamicSharedMemorySize, SMEM_GEMM);

    copy_gate_kernel<<<NROWS / 8, 256>>>(hidden, w_copy, b_copy);
    pack_split<<<256, 256>>>(hidden, Ahi, Alo, NROWS * HID / 4);
    pack_hi<<<2048, 256>>>(W_out, Bhi, VTGT * HID / 4);
    gemm_mma<<<dim3(NROWS / 128, VTGT / 256), 512, SMEM_GEMM>>>(b_out, out);
    ext_kernel<<<NROWS, 256>>>(attn, c2e, out);
    softmax_fin<<<NROWS, 256>>>(out);
}